// round 8
// baseline (speedup 1.0000x reference)
#include <cuda_runtime.h>
#include <cuda_fp16.h>
#include <math.h>
#include <stdint.h>

#define NROWS 32768      // B*S
#define FFN   2048
#define EMB   512

// ---------------- scratch ---------------------------------------------------
__device__ float  g_EV[NROWS * 8];                 // 1 MB
__device__ __half g_H[(size_t)NROWS * FFN];        // 128 MB (fp16 of H)
__device__ __half g_Wh[EMB * FFN];                 // 2 MB  (fp16 hi of 1024*W2)
__device__ __half g_Wl[EMB * FFN];                 // 2 MB  (fp16 lo of 1024*W2)

// ---------------------------------------------------------------------------
// Kernel 1: quantum circuit collapsed to closed form (verified R1/R2).
// ---------------------------------------------------------------------------
__global__ void ev_kernel(const float* __restrict__ x,
                          const float* __restrict__ params) {
    int row = blockIdx.x * blockDim.x + threadIdx.x;
    if (row >= NROWS) return;
    float z[8];
#pragma unroll
    for (int i = 0; i < 8; i++) {
        float a = params[i * 3 + 0];
        float b = params[i * 3 + 1];
        float c = params[i * 3 + 2];
        float sa, ca, sb, cb, sc, cc;
        sincosf(a, &sa, &ca);
        sincosf(b, &sb, &cb);
        sincosf(c, &sc, &cc);
        float Acoef = ca * cc + sa * sb * sc;
        float Ccoef = cb * sc;
        float sx, cx;
        sincosf(x[row * 8 + i], &sx, &cx);
        z[i] = Acoef * cx - Ccoef * sx;
    }
    float ev[8];
    float pre = z[0];
#pragma unroll
    for (int k = 1; k < 8; k++) { pre *= z[k]; ev[k] = pre; }
    float suf = 1.0f;
#pragma unroll
    for (int k = 7; k >= 1; k--) suf *= z[k];
    ev[0] = suf;
    float4* out = (float4*)&g_EV[row * 8];
    out[0] = make_float4(ev[0], ev[1], ev[2], ev[3]);
    out[1] = make_float4(ev[4], ev[5], ev[6], ev[7]);
}

// ---------------------------------------------------------------------------
// Kernel 2: H = relu(EV @ W1^T + b1) -> fp16.  (R6-proven: col-owning threads)
// ---------------------------------------------------------------------------
#define HROWS 64
__global__ void __launch_bounds__(256)
h_half_kernel(const float* __restrict__ W1, const float* __restrict__ b1) {
    int c0 = blockIdx.x * 512 + threadIdx.x * 2;
    int r0 = blockIdx.y * HROWS;
    float4 wa0 = *(const float4*)&W1[c0 * 8];
    float4 wa1 = *(const float4*)&W1[c0 * 8 + 4];
    float4 wb0 = *(const float4*)&W1[(c0 + 1) * 8];
    float4 wb1 = *(const float4*)&W1[(c0 + 1) * 8 + 4];
    float ba = b1[c0], bb = b1[c0 + 1];
#pragma unroll 4
    for (int r = r0; r < r0 + HROWS; r++) {
        float4 e0 = *(const float4*)&g_EV[r * 8];
        float4 e1 = *(const float4*)&g_EV[r * 8 + 4];
        float ha = ba
                 + e0.x * wa0.x + e0.y * wa0.y + e0.z * wa0.z + e0.w * wa0.w
                 + e1.x * wa1.x + e1.y * wa1.y + e1.z * wa1.z + e1.w * wa1.w;
        float hb = bb
                 + e0.x * wb0.x + e0.y * wb0.y + e0.z * wb0.z + e0.w * wb0.w
                 + e1.x * wb1.x + e1.y * wb1.y + e1.z * wb1.z + e1.w * wb1.w;
        __half2 hv = __floats2half2_rn(fmaxf(ha, 0.0f), fmaxf(hb, 0.0f));
        *(__half2*)&g_H[(size_t)r * FFN + c0] = hv;
    }
}

// ---------------------------------------------------------------------------
// Kernel 3: split 1024*W2 into fp16 hi/lo
// ---------------------------------------------------------------------------
__global__ void w_split_kernel(const float* __restrict__ W2) {
    int idx = blockIdx.x * blockDim.x + threadIdx.x;
    float2 v = ((const float2*)W2)[idx];
    float v0 = v.x * 1024.0f, v1 = v.y * 1024.0f;
    __half h0 = __float2half(v0);
    __half h1 = __float2half(v1);
    __half l0 = __float2half(v0 - __half2float(h0));
    __half l1 = __float2half(v1 - __half2float(h1));
    ((__half2*)g_Wh)[idx] = __halves2half2(h0, h1);
    ((__half2*)g_Wl)[idx] = __halves2half2(l0, l1);
}

// ---------------------------------------------------------------------------
// Kernel 4: OUT = H @ W2^T + b2, mma.sync fp16.
// Hi pass (Ah*Bh) -> fp32 acc; lo pass (Ah*Bl) -> fp16 acc (2x rate if avail).
// CTA 128x64x32, 4 warps (2x2, warp tile 64x32), 3-stage cp.async,
// 48KB static smem, 4 CTAs/SM.  (R7-proven skeleton.)
// ---------------------------------------------------------------------------
#define BM 128
#define BN 64
#define BK 32
#define NT (FFN / BK)             // 64
#define STG 16384                 // A 0 (8192), Bh 8192 (4096), Bl 12288 (4096)

#define CP16(dst, src) \
    asm volatile("cp.async.cg.shared.global [%0], [%1], 16;\n" :: "r"(dst), "l"(src))

__device__ __forceinline__ void ldsm4(unsigned* r, unsigned a) {
    asm volatile("ldmatrix.sync.aligned.m8n8.x4.shared.b16 {%0,%1,%2,%3}, [%4];"
                 : "=r"(r[0]), "=r"(r[1]), "=r"(r[2]), "=r"(r[3]) : "r"(a));
}

__device__ __forceinline__ void mma16816(float* c, const unsigned* a, const unsigned* b) {
    asm volatile("mma.sync.aligned.m16n8k16.row.col.f32.f16.f16.f32 "
                 "{%0,%1,%2,%3}, {%4,%5,%6,%7}, {%8,%9}, {%0,%1,%2,%3};"
                 : "+f"(c[0]), "+f"(c[1]), "+f"(c[2]), "+f"(c[3])
                 : "r"(a[0]), "r"(a[1]), "r"(a[2]), "r"(a[3]), "r"(b[0]), "r"(b[1]));
}

__device__ __forceinline__ void mma16816h(unsigned* c, const unsigned* a, const unsigned* b) {
    asm volatile("mma.sync.aligned.m16n8k16.row.col.f16.f16.f16.f16 "
                 "{%0,%1}, {%2,%3,%4,%5}, {%6,%7}, {%0,%1};"
                 : "+r"(c[0]), "+r"(c[1])
                 : "r"(a[0]), "r"(a[1]), "r"(a[2]), "r"(a[3]), "r"(b[0]), "r"(b[1]));
}

__device__ __forceinline__ unsigned swz(int row, int ch) {  // 64B rows, 16B chunks
    return (unsigned)(row * 64 + ((ch ^ ((row >> 1) & 3)) << 4));
}

__device__ __forceinline__ void load_stage(unsigned st, int bm, int bn, int tid, int k0) {
#pragma unroll
    for (int i = 0; i < 4; i++) {               // A: 512 chunks of 16B
        int id = tid + (i << 7);
        int r = id >> 2, c = id & 3;
        size_t g = (size_t)(bm + r) * FFN + k0 + c * 8;
        CP16(st + swz(r, c), g_H + g);
    }
#pragma unroll
    for (int i = 0; i < 2; i++) {               // B: 256 chunks each hi/lo
        int id = tid + (i << 7);
        int r = id >> 2, c = id & 3;
        unsigned so = swz(r, c);
        size_t g = (size_t)(bn + r) * FFN + k0 + c * 8;
        CP16(st + 8192 + so,  g_Wh + g);
        CP16(st + 12288 + so, g_Wl + g);
    }
}

__global__ void __launch_bounds__(128, 4)
mma_gemm(const float* __restrict__ bias, float* __restrict__ C) {
    __shared__ __align__(128) unsigned char smem[3 * STG];
    const int tid  = threadIdx.x;
    const int warp = tid >> 5, lane = tid & 31;
    const int wm = warp & 1;                 // 2 m-groups of 64 rows
    const int wn = warp >> 1;                // 2 n-groups of 32 cols
    const int bm = blockIdx.y * BM, bn = blockIdx.x * BN;
    const unsigned sbase = (unsigned)__cvta_generic_to_shared(smem);

    float    acc [4][4][4];                  // hi pass, fp32
    unsigned accl[4][4][2];                  // lo pass, fp16 (half2 x2)
#pragma unroll
    for (int i = 0; i < 4; i++)
#pragma unroll
        for (int j = 0; j < 4; j++) {
#pragma unroll
            for (int k = 0; k < 4; k++) acc[i][j][k] = 0.0f;
            accl[i][j][0] = 0u; accl[i][j][1] = 0u;
        }

    load_stage(sbase,       bm, bn, tid, 0);
    asm volatile("cp.async.commit_group;\n");
    load_stage(sbase + STG, bm, bn, tid, BK);
    asm volatile("cp.async.commit_group;\n");

    for (int t = 0; t < NT; t++) {
        if (t + 1 < NT) asm volatile("cp.async.wait_group 1;\n" ::: "memory");
        else            asm volatile("cp.async.wait_group 0;\n" ::: "memory");
        __syncthreads();

        if (t + 2 < NT) {
            load_stage(sbase + ((t + 2) % 3) * STG, bm, bn, tid, (t + 2) * BK);
            asm volatile("cp.async.commit_group;\n");
        }

        unsigned st = sbase + (t % 3) * STG;
#pragma unroll
        for (int kk = 0; kk < 2; kk++) {
            unsigned ah[4][4], bh[2][4], bl[2][4];
#pragma unroll
            for (int mf = 0; mf < 4; mf++) {     // A frags: m64 x k16
                int r  = wm * 64 + mf * 16 + (lane & 15);
                int ch = kk * 2 + (lane >> 4);
                ldsm4(ah[mf], st + swz(r, ch));
            }
#pragma unroll
            for (int nb = 0; nb < 2; nb++) {     // B frags: n32 hi+lo
                int n  = wn * 32 + nb * 16 + (lane & 7) + ((lane >> 4) & 1) * 8;
                int ch = kk * 2 + ((lane >> 3) & 1);
                unsigned a = st + 8192 + swz(n, ch);
                ldsm4(bh[nb], a);
                ldsm4(bl[nb], a + 4096);
            }
#pragma unroll
            for (int mf = 0; mf < 4; mf++)
#pragma unroll
                for (int nf = 0; nf < 4; nf++) {
                    const unsigned* bhp = &bh[nf >> 1][(nf & 1) * 2];
                    const unsigned* blp = &bl[nf >> 1][(nf & 1) * 2];
                    mma16816 (acc [mf][nf], ah[mf], bhp);   // Ah*Bh  (fp32 acc)
                    mma16816h(accl[mf][nf], ah[mf], blp);   // Ah*Bl  (fp16 acc)
                }
        }
    }

    // epilogue: combine hi + lo, undo 1024x W2 scaling, add bias
    const float inv = 1.0f / 1024.0f;
#pragma unroll
    for (int mf = 0; mf < 4; mf++) {
        int r0 = bm + wm * 64 + mf * 16 + (lane >> 2);
#pragma unroll
        for (int nf = 0; nf < 4; nf++) {
            int cc = bn + wn * 32 + nf * 8 + (lane & 3) * 2;
            float2 b2 = *(const float2*)&bias[cc];
            float2 l0 = __half22float2(*(__half2*)&accl[mf][nf][0]);
            float2 l1 = __half22float2(*(__half2*)&accl[mf][nf][1]);
            float2 v0 = make_float2((acc[mf][nf][0] + l0.x) * inv + b2.x,
                                    (acc[mf][nf][1] + l0.y) * inv + b2.y);
            float2 v1 = make_float2((acc[mf][nf][2] + l1.x) * inv + b2.x,
                                    (acc[mf][nf][3] + l1.y) * inv + b2.y);
            *(float2*)&C[(size_t)r0 * EMB + cc]       = v0;
            *(float2*)&C[(size_t)(r0 + 8) * EMB + cc] = v1;
        }
    }
}

// ---------------------------------------------------------------------------
extern "C" void kernel_launch(void* const* d_in, const int* in_sizes, int n_in,
                              void* d_out, int out_size) {
    const float* x      = (const float*)d_in[0];  // [16,2048,8]
    const float* params = (const float*)d_in[1];  // [8,3]
    const float* W1     = (const float*)d_in[2];  // [2048,8]
    const float* b1     = (const float*)d_in[3];  // [2048]
    const float* W2     = (const float*)d_in[4];  // [512,2048]
    const float* b2     = (const float*)d_in[5];  // [512]
    float* out = (float*)d_out;                   // [16,2048,512]

    w_split_kernel<<<(EMB * (FFN / 2)) / 256, 256>>>(W2);
    ev_kernel<<<NROWS / 256, 256>>>(x, params);
    h_half_kernel<<<dim3(FFN / 512, NROWS / HROWS), 256>>>(W1, b1);
    mma_gemm<<<dim3(EMB / BN, NROWS / BM), 128>>>(b2, out);
}

// round 9
// speedup vs baseline: 1.1152x; 1.1152x over previous
#include <cuda_runtime.h>
#include <cuda_fp16.h>
#include <math.h>
#include <stdint.h>

#define NROWS 32768      // B*S
#define FFN   2048
#define EMB   512

// ---------------- scratch ---------------------------------------------------
__device__ float  g_EV[NROWS * 8];                 // 1 MB
__device__ __half g_H[(size_t)NROWS * FFN];        // 128 MB (fp16 of H)
__device__ __half g_Wh[EMB * FFN];                 // 2 MB  (fp16 hi of 1024*W2)
__device__ __half g_Wl[EMB * FFN];                 // 2 MB  (fp16 lo of 1024*W2)

// ---------------------------------------------------------------------------
// Kernel 1: quantum circuit collapsed to closed form (verified R1/R2).
// ---------------------------------------------------------------------------
__global__ void ev_kernel(const float* __restrict__ x,
                          const float* __restrict__ params) {
    int row = blockIdx.x * blockDim.x + threadIdx.x;
    if (row >= NROWS) return;
    float z[8];
#pragma unroll
    for (int i = 0; i < 8; i++) {
        float a = params[i * 3 + 0];
        float b = params[i * 3 + 1];
        float c = params[i * 3 + 2];
        float sa, ca, sb, cb, sc, cc;
        sincosf(a, &sa, &ca);
        sincosf(b, &sb, &cb);
        sincosf(c, &sc, &cc);
        float Acoef = ca * cc + sa * sb * sc;
        float Ccoef = cb * sc;
        float sx, cx;
        sincosf(x[row * 8 + i], &sx, &cx);
        z[i] = Acoef * cx - Ccoef * sx;
    }
    float ev[8];
    float pre = z[0];
#pragma unroll
    for (int k = 1; k < 8; k++) { pre *= z[k]; ev[k] = pre; }
    float suf = 1.0f;
#pragma unroll
    for (int k = 7; k >= 1; k--) suf *= z[k];
    ev[0] = suf;
    float4* out = (float4*)&g_EV[row * 8];
    out[0] = make_float4(ev[0], ev[1], ev[2], ev[3]);
    out[1] = make_float4(ev[4], ev[5], ev[6], ev[7]);
}

// ---------------------------------------------------------------------------
// Kernel 2: H = relu(EV @ W1^T + b1) -> fp16.  (R6-proven: col-owning threads)
// ---------------------------------------------------------------------------
#define HROWS 64
__global__ void __launch_bounds__(256)
h_half_kernel(const float* __restrict__ W1, const float* __restrict__ b1) {
    int c0 = blockIdx.x * 512 + threadIdx.x * 2;
    int r0 = blockIdx.y * HROWS;
    float4 wa0 = *(const float4*)&W1[c0 * 8];
    float4 wa1 = *(const float4*)&W1[c0 * 8 + 4];
    float4 wb0 = *(const float4*)&W1[(c0 + 1) * 8];
    float4 wb1 = *(const float4*)&W1[(c0 + 1) * 8 + 4];
    float ba = b1[c0], bb = b1[c0 + 1];
#pragma unroll 4
    for (int r = r0; r < r0 + HROWS; r++) {
        float4 e0 = *(const float4*)&g_EV[r * 8];
        float4 e1 = *(const float4*)&g_EV[r * 8 + 4];
        float ha = ba
                 + e0.x * wa0.x + e0.y * wa0.y + e0.z * wa0.z + e0.w * wa0.w
                 + e1.x * wa1.x + e1.y * wa1.y + e1.z * wa1.z + e1.w * wa1.w;
        float hb = bb
                 + e0.x * wb0.x + e0.y * wb0.y + e0.z * wb0.z + e0.w * wb0.w
                 + e1.x * wb1.x + e1.y * wb1.y + e1.z * wb1.z + e1.w * wb1.w;
        __half2 hv = __floats2half2_rn(fmaxf(ha, 0.0f), fmaxf(hb, 0.0f));
        *(__half2*)&g_H[(size_t)r * FFN + c0] = hv;
    }
}

// ---------------------------------------------------------------------------
// Kernel 3: split 1024*W2 into fp16 hi/lo
// ---------------------------------------------------------------------------
__global__ void w_split_kernel(const float* __restrict__ W2) {
    int idx = blockIdx.x * blockDim.x + threadIdx.x;
    float2 v = ((const float2*)W2)[idx];
    float v0 = v.x * 1024.0f, v1 = v.y * 1024.0f;
    __half h0 = __float2half(v0);
    __half h1 = __float2half(v1);
    __half l0 = __float2half(v0 - __half2float(h0));
    __half l1 = __float2half(v1 - __half2float(h1));
    ((__half2*)g_Wh)[idx] = __halves2half2(h0, h1);
    ((__half2*)g_Wl)[idx] = __halves2half2(l0, l1);
}

// ---------------------------------------------------------------------------
// Kernel 4: OUT = H @ W2^T + b2, mma.sync fp16 2-pass (fp32 acc, R7 math).
// CTA 128x64, BK=64, 4 warps (2x2, warp tile 64x32), 3-stage cp.async,
// 96KB dynamic smem, 2 CTAs/SM, single barrier per stage (32 stages).
// ---------------------------------------------------------------------------
#define BM 128
#define BN 64
#define BK 64
#define NT (FFN / BK)             // 32
// stage layout (bytes): A 0 (16384), Bh 16384 (8192), Bl 24576 (8192)
#define STG 32768
#define SMEM_TOTAL (3 * STG)      // 98304

#define CP16(dst, src) \
    asm volatile("cp.async.cg.shared.global [%0], [%1], 16;\n" :: "r"(dst), "l"(src))

__device__ __forceinline__ void ldsm4(unsigned* r, unsigned a) {
    asm volatile("ldmatrix.sync.aligned.m8n8.x4.shared.b16 {%0,%1,%2,%3}, [%4];"
                 : "=r"(r[0]), "=r"(r[1]), "=r"(r[2]), "=r"(r[3]) : "r"(a));
}

__device__ __forceinline__ void mma16816(float* c, const unsigned* a, const unsigned* b) {
    asm volatile("mma.sync.aligned.m16n8k16.row.col.f32.f16.f16.f32 "
                 "{%0,%1,%2,%3}, {%4,%5,%6,%7}, {%8,%9}, {%0,%1,%2,%3};"
                 : "+f"(c[0]), "+f"(c[1]), "+f"(c[2]), "+f"(c[3])
                 : "r"(a[0]), "r"(a[1]), "r"(a[2]), "r"(a[3]), "r"(b[0]), "r"(b[1]));
}

// 128B rows, 8 chunks of 16B, full SW128 swizzle
__device__ __forceinline__ unsigned swz(int row, int ch) {
    return (unsigned)(row * 128 + ((ch ^ (row & 7)) << 4));
}

__device__ __forceinline__ void load_stage(unsigned st, int bm, int bn, int tid, int k0) {
#pragma unroll
    for (int i = 0; i < 8; i++) {               // A: 1024 chunks of 16B
        int id = tid + (i << 7);
        int r = id >> 3, c = id & 7;
        size_t g = (size_t)(bm + r) * FFN + k0 + c * 8;
        CP16(st + swz(r, c), g_H + g);
    }
#pragma unroll
    for (int i = 0; i < 4; i++) {               // B: 512 chunks each hi/lo
        int id = tid + (i << 7);
        int r = id >> 3, c = id & 7;
        unsigned so = swz(r, c);
        size_t g = (size_t)(bn + r) * FFN + k0 + c * 8;
        CP16(st + 16384 + so, g_Wh + g);
        CP16(st + 24576 + so, g_Wl + g);
    }
}

__global__ void __launch_bounds__(128, 2)
mma_gemm(const float* __restrict__ bias, float* __restrict__ C) {
    extern __shared__ __align__(128) unsigned char smem[];
    const int tid  = threadIdx.x;
    const int warp = tid >> 5, lane = tid & 31;
    const int wm = warp & 1;                 // 2 m-groups of 64 rows
    const int wn = warp >> 1;                // 2 n-groups of 32 cols
    const int bm = blockIdx.y * BM, bn = blockIdx.x * BN;
    const unsigned sbase = (unsigned)__cvta_generic_to_shared(smem);

    float acc[4][4][4];                      // [mf][nf][frag]
#pragma unroll
    for (int i = 0; i < 4; i++)
#pragma unroll
        for (int j = 0; j < 4; j++)
#pragma unroll
            for (int k = 0; k < 4; k++) acc[i][j][k] = 0.0f;

    load_stage(sbase,       bm, bn, tid, 0);
    asm volatile("cp.async.commit_group;\n");
    load_stage(sbase + STG, bm, bn, tid, BK);
    asm volatile("cp.async.commit_group;\n");

    for (int t = 0; t < NT; t++) {
        if (t + 1 < NT) asm volatile("cp.async.wait_group 1;\n" ::: "memory");
        else            asm volatile("cp.async.wait_group 0;\n" ::: "memory");
        __syncthreads();          // single barrier per stage (3-stage ring)

        if (t + 2 < NT) {
            load_stage(sbase + ((t + 2) % 3) * STG, bm, bn, tid, (t + 2) * BK);
            asm volatile("cp.async.commit_group;\n");
        }

        unsigned st = sbase + (t % 3) * STG;
#pragma unroll
        for (int kk = 0; kk < 4; kk++) {     // four k16 chunks of BK=64
            unsigned ah[4][4], bh[2][4], bl[2][4];
#pragma unroll
            for (int mf = 0; mf < 4; mf++) {     // A frags: m64 x k16
                int r  = wm * 64 + mf * 16 + (lane & 15);
                int ch = kk * 2 + (lane >> 4);
                ldsm4(ah[mf], st + swz(r, ch));
            }
#pragma unroll
            for (int nb = 0; nb < 2; nb++) {     // B frags: n32 hi+lo
                int n  = wn * 32 + nb * 16 + (lane & 7) + ((lane >> 4) & 1) * 8;
                int ch = kk * 2 + ((lane >> 3) & 1);
                unsigned a = st + 16384 + swz(n, ch);
                ldsm4(bh[nb], a);
                ldsm4(bl[nb], a + 8192);
            }
#pragma unroll
            for (int mf = 0; mf < 4; mf++)
#pragma unroll
                for (int nf = 0; nf < 4; nf++) {
                    const unsigned* bhp = &bh[nf >> 1][(nf & 1) * 2];
                    const unsigned* blp = &bl[nf >> 1][(nf & 1) * 2];
                    mma16816(acc[mf][nf], ah[mf], bhp);   // Ah*Bh
                    mma16816(acc[mf][nf], ah[mf], blp);   // Ah*Bl
                }
        }
    }

    // epilogue: undo the 1024x W2 scaling, add bias
    const float inv = 1.0f / 1024.0f;
#pragma unroll
    for (int mf = 0; mf < 4; mf++) {
        int r0 = bm + wm * 64 + mf * 16 + (lane >> 2);
#pragma unroll
        for (int nf = 0; nf < 4; nf++) {
            int cc = bn + wn * 32 + nf * 8 + (lane & 3) * 2;
            float2 b2 = *(const float2*)&bias[cc];
            float2 v0 = make_float2(acc[mf][nf][0] * inv + b2.x,
                                    acc[mf][nf][1] * inv + b2.y);
            float2 v1 = make_float2(acc[mf][nf][2] * inv + b2.x,
                                    acc[mf][nf][3] * inv + b2.y);
            *(float2*)&C[(size_t)r0 * EMB + cc]       = v0;
            *(float2*)&C[(size_t)(r0 + 8) * EMB + cc] = v1;
        }
    }
}

// ---------------------------------------------------------------------------
extern "C" void kernel_launch(void* const* d_in, const int* in_sizes, int n_in,
                              void* d_out, int out_size) {
    const float* x      = (const float*)d_in[0];  // [16,2048,8]
    const float* params = (const float*)d_in[1];  // [8,3]
    const float* W1     = (const float*)d_in[2];  // [2048,8]
    const float* b1     = (const float*)d_in[3];  // [2048]
    const float* W2     = (const float*)d_in[4];  // [512,2048]
    const float* b2     = (const float*)d_in[5];  // [512]
    float* out = (float*)d_out;                   // [16,2048,512]

    cudaFuncSetAttribute(mma_gemm, cudaFuncAttributeMaxDynamicSharedMemorySize,
                         SMEM_TOTAL);

    w_split_kernel<<<(EMB * (FFN / 2)) / 256, 256>>>(W2);
    ev_kernel<<<NROWS / 256, 256>>>(x, params);
    h_half_kernel<<<dim3(FFN / 512, NROWS / HROWS), 256>>>(W1, b1);
    mma_gemm<<<dim3(EMB / BN, NROWS / BM), 128, SMEM_TOTAL>>>(b2, out);
}

// round 10
// speedup vs baseline: 1.7864x; 1.6018x over previous
#include <cuda_runtime.h>
#include <cuda_fp16.h>
#include <math.h>
#include <stdint.h>

#define NROWS 32768      // B*S
#define FFN   2048
#define EMB   512

// ---------------- scratch ---------------------------------------------------
__device__ float  g_EV[NROWS * 8];                 // 1 MB
__device__ __half g_H[(size_t)NROWS * FFN];        // 128 MB (fp16 of H)
__device__ __half g_Wh[EMB * FFN];                 // 2 MB  (fp16 of W2)

// ---------------------------------------------------------------------------
// Kernel 1: quantum circuit collapsed to closed form (verified R1/R2).
// ---------------------------------------------------------------------------
__global__ void ev_kernel(const float* __restrict__ x,
                          const float* __restrict__ params) {
    int row = blockIdx.x * blockDim.x + threadIdx.x;
    if (row >= NROWS) return;
    float z[8];
#pragma unroll
    for (int i = 0; i < 8; i++) {
        float a = params[i * 3 + 0];
        float b = params[i * 3 + 1];
        float c = params[i * 3 + 2];
        float sa, ca, sb, cb, sc, cc;
        sincosf(a, &sa, &ca);
        sincosf(b, &sb, &cb);
        sincosf(c, &sc, &cc);
        float Acoef = ca * cc + sa * sb * sc;
        float Ccoef = cb * sc;
        float sx, cx;
        sincosf(x[row * 8 + i], &sx, &cx);
        z[i] = Acoef * cx - Ccoef * sx;
    }
    float ev[8];
    float pre = z[0];
#pragma unroll
    for (int k = 1; k < 8; k++) { pre *= z[k]; ev[k] = pre; }
    float suf = 1.0f;
#pragma unroll
    for (int k = 7; k >= 1; k--) suf *= z[k];
    ev[0] = suf;
    float4* out = (float4*)&g_EV[row * 8];
    out[0] = make_float4(ev[0], ev[1], ev[2], ev[3]);
    out[1] = make_float4(ev[4], ev[5], ev[6], ev[7]);
}

// ---------------------------------------------------------------------------
// Kernel 2: H = relu(EV @ W1^T + b1) -> fp16.  (R6-proven: col-owning threads)
// ---------------------------------------------------------------------------
#define HROWS 64
__global__ void __launch_bounds__(256)
h_half_kernel(const float* __restrict__ W1, const float* __restrict__ b1) {
    int c0 = blockIdx.x * 512 + threadIdx.x * 2;
    int r0 = blockIdx.y * HROWS;
    float4 wa0 = *(const float4*)&W1[c0 * 8];
    float4 wa1 = *(const float4*)&W1[c0 * 8 + 4];
    float4 wb0 = *(const float4*)&W1[(c0 + 1) * 8];
    float4 wb1 = *(const float4*)&W1[(c0 + 1) * 8 + 4];
    float ba = b1[c0], bb = b1[c0 + 1];
#pragma unroll 4
    for (int r = r0; r < r0 + HROWS; r++) {
        float4 e0 = *(const float4*)&g_EV[r * 8];
        float4 e1 = *(const float4*)&g_EV[r * 8 + 4];
        float ha = ba
                 + e0.x * wa0.x + e0.y * wa0.y + e0.z * wa0.z + e0.w * wa0.w
                 + e1.x * wa1.x + e1.y * wa1.y + e1.z * wa1.z + e1.w * wa1.w;
        float hb = bb
                 + e0.x * wb0.x + e0.y * wb0.y + e0.z * wb0.z + e0.w * wb0.w
                 + e1.x * wb1.x + e1.y * wb1.y + e1.z * wb1.z + e1.w * wb1.w;
        __half2 hv = __floats2half2_rn(fmaxf(ha, 0.0f), fmaxf(hb, 0.0f));
        *(__half2*)&g_H[(size_t)r * FFN + c0] = hv;
    }
}

// ---------------------------------------------------------------------------
// Kernel 3: W2 -> fp16 (single precision level; no scaling needed)
// ---------------------------------------------------------------------------
__global__ void w_half_kernel(const float* __restrict__ W2) {
    int idx = blockIdx.x * blockDim.x + threadIdx.x;   // [0, EMB*FFN/2)
    float2 v = ((const float2*)W2)[idx];
    ((__half2*)g_Wh)[idx] = __floats2half2_rn(v.x, v.y);
}

// ---------------------------------------------------------------------------
// Kernel 4: OUT = H @ W2^T + b2, mma.sync fp16 SINGLE pass, fp32 acc.
// CTA 128x64, BK=64, 4 warps (2x2, warp tile 64x32), 3-stage cp.async,
// 72KB dynamic smem, 3 CTAs/SM.  (R9 skeleton minus the lo pass.)
// ---------------------------------------------------------------------------
#define BM 128
#define BN 64
#define BK 64
#define NT (FFN / BK)             // 32
// stage layout (bytes): A 0 (16384), B 16384 (8192)
#define STG 24576
#define SMEM_TOTAL (3 * STG)      // 73728

#define CP16(dst, src) \
    asm volatile("cp.async.cg.shared.global [%0], [%1], 16;\n" :: "r"(dst), "l"(src))

__device__ __forceinline__ void ldsm4(unsigned* r, unsigned a) {
    asm volatile("ldmatrix.sync.aligned.m8n8.x4.shared.b16 {%0,%1,%2,%3}, [%4];"
                 : "=r"(r[0]), "=r"(r[1]), "=r"(r[2]), "=r"(r[3]) : "r"(a));
}

__device__ __forceinline__ void mma16816(float* c, const unsigned* a, const unsigned* b) {
    asm volatile("mma.sync.aligned.m16n8k16.row.col.f32.f16.f16.f32 "
                 "{%0,%1,%2,%3}, {%4,%5,%6,%7}, {%8,%9}, {%0,%1,%2,%3};"
                 : "+f"(c[0]), "+f"(c[1]), "+f"(c[2]), "+f"(c[3])
                 : "r"(a[0]), "r"(a[1]), "r"(a[2]), "r"(a[3]), "r"(b[0]), "r"(b[1]));
}

// 128B rows, 8 chunks of 16B, full SW128 swizzle
__device__ __forceinline__ unsigned swz(int row, int ch) {
    return (unsigned)(row * 128 + ((ch ^ (row & 7)) << 4));
}

__device__ __forceinline__ void load_stage(unsigned st, int bm, int bn, int tid, int k0) {
#pragma unroll
    for (int i = 0; i < 8; i++) {               // A: 1024 chunks of 16B
        int id = tid + (i << 7);
        int r = id >> 3, c = id & 7;
        size_t g = (size_t)(bm + r) * FFN + k0 + c * 8;
        CP16(st + swz(r, c), g_H + g);
    }
#pragma unroll
    for (int i = 0; i < 4; i++) {               // B: 512 chunks of 16B
        int id = tid + (i << 7);
        int r = id >> 3, c = id & 7;
        size_t g = (size_t)(bn + r) * FFN + k0 + c * 8;
        CP16(st + 16384 + swz(r, c), g_Wh + g);
    }
}

__global__ void __launch_bounds__(128, 3)
mma_gemm(const float* __restrict__ bias, float* __restrict__ C) {
    extern __shared__ __align__(128) unsigned char smem[];
    const int tid  = threadIdx.x;
    const int warp = tid >> 5, lane = tid & 31;
    const int wm = warp & 1;                 // 2 m-groups of 64 rows
    const int wn = warp >> 1;                // 2 n-groups of 32 cols
    const int bm = blockIdx.y * BM, bn = blockIdx.x * BN;
    const unsigned sbase = (unsigned)__cvta_generic_to_shared(smem);

    float acc[4][4][4];                      // [mf][nf][frag]
#pragma unroll
    for (int i = 0; i < 4; i++)
#pragma unroll
        for (int j = 0; j < 4; j++)
#pragma unroll
            for (int k = 0; k < 4; k++) acc[i][j][k] = 0.0f;

    load_stage(sbase,       bm, bn, tid, 0);
    asm volatile("cp.async.commit_group;\n");
    load_stage(sbase + STG, bm, bn, tid, BK);
    asm volatile("cp.async.commit_group;\n");

    for (int t = 0; t < NT; t++) {
        if (t + 1 < NT) asm volatile("cp.async.wait_group 1;\n" ::: "memory");
        else            asm volatile("cp.async.wait_group 0;\n" ::: "memory");
        __syncthreads();          // single barrier per stage (3-stage ring)

        if (t + 2 < NT) {
            load_stage(sbase + ((t + 2) % 3) * STG, bm, bn, tid, (t + 2) * BK);
            asm volatile("cp.async.commit_group;\n");
        }

        unsigned st = sbase + (t % 3) * STG;
#pragma unroll
        for (int kk = 0; kk < 4; kk++) {     // four k16 chunks of BK=64
            unsigned ah[4][4], bh[2][4];
#pragma unroll
            for (int mf = 0; mf < 4; mf++) {     // A frags: m64 x k16
                int r  = wm * 64 + mf * 16 + (lane & 15);
                int ch = kk * 2 + (lane >> 4);
                ldsm4(ah[mf], st + swz(r, ch));
            }
#pragma unroll
            for (int nb = 0; nb < 2; nb++) {     // B frags: n32
                int n  = wn * 32 + nb * 16 + (lane & 7) + ((lane >> 4) & 1) * 8;
                int ch = kk * 2 + ((lane >> 3) & 1);
                ldsm4(bh[nb], st + 16384 + swz(n, ch));
            }
#pragma unroll
            for (int mf = 0; mf < 4; mf++)
#pragma unroll
                for (int nf = 0; nf < 4; nf++)
                    mma16816(acc[mf][nf], ah[mf], &bh[nf >> 1][(nf & 1) * 2]);
        }
    }

    // epilogue: add bias
#pragma unroll
    for (int mf = 0; mf < 4; mf++) {
        int r0 = bm + wm * 64 + mf * 16 + (lane >> 2);
#pragma unroll
        for (int nf = 0; nf < 4; nf++) {
            int cc = bn + wn * 32 + nf * 8 + (lane & 3) * 2;
            float2 b2 = *(const float2*)&bias[cc];
            float2 v0 = make_float2(acc[mf][nf][0] + b2.x, acc[mf][nf][1] + b2.y);
            float2 v1 = make_float2(acc[mf][nf][2] + b2.x, acc[mf][nf][3] + b2.y);
            *(float2*)&C[(size_t)r0 * EMB + cc]       = v0;
            *(float2*)&C[(size_t)(r0 + 8) * EMB + cc] = v1;
        }
    }
}

// ---------------------------------------------------------------------------
extern "C" void kernel_launch(void* const* d_in, const int* in_sizes, int n_in,
                              void* d_out, int out_size) {
    const float* x      = (const float*)d_in[0];  // [16,2048,8]
    const float* params = (const float*)d_in[1];  // [8,3]
    const float* W1     = (const float*)d_in[2];  // [2048,8]
    const float* b1     = (const float*)d_in[3];  // [2048]
    const float* W2     = (const float*)d_in[4];  // [512,2048]
    const float* b2     = (const float*)d_in[5];  // [512]
    float* out = (float*)d_out;                   // [16,2048,512]

    cudaFuncSetAttribute(mma_gemm, cudaFuncAttributeMaxDynamicSharedMemorySize,
                         SMEM_TOTAL);

    w_half_kernel<<<(EMB * (FFN / 2)) / 256, 256>>>(W2);
    ev_kernel<<<NROWS / 256, 256>>>(x, params);
    h_half_kernel<<<dim3(FFN / 512, NROWS / HROWS), 256>>>(W1, b1);
    mma_gemm<<<dim3(EMB / BN, NROWS / BM), 128, SMEM_TOTAL>>>(b2, out);
}